// round 5
// baseline (speedup 1.0000x reference)
#include <cuda_runtime.h>
#include <cuda_bf16.h>

// Output layout (float32 elements, concatenated in reference return order):
//   [0, B*NP*FEAT)      batch          (B, NP, FEAT)
//   [+, B*NP)           proposal_mask  (B, NP)
//   [+, P)              scores_pred    (P,)
//   [+, B*NP*K)         proposal_ious  (B, NP, K)
//   [+, P*N_POINTS)     proposals_pred (P, N_POINTS)

static constexpr int NUM_PROPOSAL = 256;

static constexpr int CHUNK = 131072;          // floats per block (512 KB out)
static constexpr int BM_WORDS = CHUNK / 32;   // 4096 words = 16 KB smem
static constexpr int THREADS = 512;           // 16 warps
static constexpr int WARPS = THREADS / 32;
static constexpr int TILES = BM_WORDS / 32;   // 128 warp-tiles per block

// ---------------------------------------------------------------------------
// Small per-proposal kernel: single block of P threads.
// ---------------------------------------------------------------------------
__global__ void refnet_small_kernel(
    const float* __restrict__ scores,   // (P,1)
    const float* __restrict__ feats,    // (P,FEAT)
    const float* __restrict__ ious,     // (P,K)
    const int*   __restrict__ pidx,     // (M,2) int32
    const int*   __restrict__ poff,     // (P+1,) int32
    const int*   __restrict__ boff,     // (B+1,) int32
    float* __restrict__ out,
    int P, int FEAT, int K, int B,
    long long off_batch, long long off_mask, long long off_scores, long long off_ious)
{
    __shared__ int b_arr[1024];
    int p = threadIdx.x;
    if (p >= P) return;

    float s = scores[p];
    out[off_scores + p] = 1.0f / (1.0f + expf(-s));

    int o = poff[p];
    int first_pt = pidx[2 * o + 1];
    int b = 0;
    for (int i = 1; i <= B; ++i) {
        if (boff[i] <= first_pt) b = i;   // searchsorted(right) - 1
    }
    b_arr[p] = b;
    __syncthreads();

    int slot = 0;
    for (int q = 0; q < p; ++q) slot += (b_arr[q] == b);

    long long base = (long long)b * NUM_PROPOSAL + slot;
    out[off_mask + base] = 1.0f;

    const float* fsrc = feats + (long long)p * FEAT;
    float* fdst = out + off_batch + base * FEAT;
    for (int i = 0; i < FEAT; ++i) fdst[i] = fsrc[i];

    const float* isrc = ious + (long long)p * K;
    float* idst = out + off_ious + base * K;
    for (int i = 0; i < K; ++i) idst[i] = isrc[i];
}

// ---------------------------------------------------------------------------
// Fused zero+scatter for proposals_pred.
// Row p's points are the contiguous slice pidx[poff[p]:poff[p+1]], and all
// of them lie inside the row's batch column range [boff[b], boff[b+1]).
// Chunks that don't intersect that range are pure zero -> streaming fill,
// no smem / no index scan. Intersecting chunks use the smem bitmap +
// warp-tile-transposed expansion (fully coalesced STG.128).
// ---------------------------------------------------------------------------
__global__ void __launch_bounds__(THREADS)
refnet_render_kernel(
    const int2* __restrict__ pidx,   // (M) pairs (pid, ptid)
    const int*  __restrict__ poff,   // (P+1,)
    const int*  __restrict__ boff,   // (B+1,)
    float* __restrict__ pp,          // proposals_pred base
    long long n_points, int chunks_per_row, int B)
{
    __shared__ unsigned int bm[BM_WORDS];

    int row   = blockIdx.x / chunks_per_row;
    int chunk = blockIdx.x % chunks_per_row;
    long long c0 = (long long)chunk * CHUNK;

    int tid  = threadIdx.x;
    int warp = tid >> 5;
    int lane = tid & 31;

    float* rowbase = pp + (long long)row * n_points + c0;
    long long row_rem = n_points - c0;                 // floats in this row chunk
    int nflt = (int)(row_rem < CHUNK ? row_rem : CHUNK);

    // Row's batch column interval
    int beg = poff[row], end = poff[row + 1];
    int2 v0 = pidx[beg];
    int first_pt = v0.y;
    int b = 0;
    for (int i = 1; i <= B; ++i)
        if (boff[i] <= first_pt) b = i;
    long long lo = boff[b], hi = boff[b + 1];

    if (hi <= c0 || lo >= c0 + CHUNK) {
        // -------- pure-zero chunk: streaming fill, no smem --------
        const float4 z4 = make_float4(0.0f, 0.0f, 0.0f, 0.0f);
        float4* dst = (float4*)rowbase;
        int n4 = nflt >> 2;
        #pragma unroll 4
        for (int i = tid; i < n4; i += THREADS) dst[i] = z4;
        return;
    }

    // -------- bitmap path --------
    for (int w = tid; w < BM_WORDS; w += THREADS) bm[w] = 0u;
    __syncthreads();

    for (int i = beg + tid; i < end; i += THREADS) {
        int2 v = pidx[i];
        long long rel = (long long)v.y - c0;
        if (rel >= 0 && rel < CHUNK) {
            atomicOr(&bm[(int)(rel >> 5)], 1u << ((int)rel & 31));
        }
    }
    __syncthreads();

    // Expand: warp owns 32-word tiles (1024 floats = 4 KB each).
    // Iter j: lane L writes float4 #(j*32+L) -> consecutive lanes write
    // consecutive 16 B => each STG.128 is 512B contiguous (4 lines).
    for (int t = warp; t < TILES; t += WARPS) {
        int wb = t * 32;                          // word base of tile
        long long fbase = (long long)wb * 32;     // float base of tile
        if (fbase >= row_rem) break;
        float4* dst = (float4*)(rowbase + fbase);
        #pragma unroll
        for (int j = 0; j < 8; ++j) {
            int f = j * 32 + lane;                   // float4 index within tile
            unsigned int word = bm[wb + (f >> 3)];   // 8-lane smem broadcast
            unsigned int nib = (word >> ((f & 7) * 4)) & 0xFu;
            float4 o;
            o.x = (nib & 1u) ? 1.0f : 0.0f;
            o.y = (nib & 2u) ? 1.0f : 0.0f;
            o.z = (nib & 4u) ? 1.0f : 0.0f;
            o.w = (nib & 8u) ? 1.0f : 0.0f;
            dst[f] = o;
        }
    }
}

extern "C" void kernel_launch(void* const* d_in, const int* in_sizes, int n_in,
                              void* d_out, int out_size) {
    const float* scores = (const float*)d_in[0];
    const float* feats  = (const float*)d_in[1];
    const float* ious   = (const float*)d_in[2];
    const int*   pidx   = (const int*)d_in[3];
    const int*   poff   = (const int*)d_in[4];
    const int*   boff   = (const int*)d_in[5];

    int P    = in_sizes[0];               // 256
    int FEAT = in_sizes[1] / P;           // 16
    int K    = in_sizes[2] / P;           // 32
    int B    = in_sizes[5] - 1;           // 4

    long long off_batch  = 0;
    long long off_mask   = off_batch + (long long)B * NUM_PROPOSAL * FEAT;
    long long off_scores = off_mask  + (long long)B * NUM_PROPOSAL;
    long long off_ious   = off_scores + P;
    long long off_pp     = off_ious  + (long long)B * NUM_PROPOSAL * K;
    long long n_points   = ((long long)out_size - off_pp) / P;

    float* out = (float*)d_out;

    // 1) Zero the small head region only (~200 KB)
    cudaMemsetAsync(d_out, 0, (size_t)off_pp * sizeof(float), 0);

    // 2) Small per-proposal work (one block)
    refnet_small_kernel<<<1, P>>>(scores, feats, ious, pidx, poff, boff, out,
                                  P, FEAT, K, B,
                                  off_batch, off_mask, off_scores, off_ious);

    // 3) Fused zero+scatter render of proposals_pred
    int chunks_per_row = (int)((n_points + CHUNK - 1) / CHUNK);
    int blocks = P * chunks_per_row;
    refnet_render_kernel<<<blocks, THREADS>>>((const int2*)pidx, poff, boff,
                                              out + off_pp, n_points,
                                              chunks_per_row, B);
}

// round 6
// speedup vs baseline: 1.3161x; 1.3161x over previous
#include <cuda_runtime.h>
#include <cuda_bf16.h>

// Output layout (float32 elements, concatenated in reference return order):
//   [0, B*NP*FEAT)      batch          (B, NP, FEAT)
//   [+, B*NP)           proposal_mask  (B, NP)
//   [+, P)              scores_pred    (P,)
//   [+, B*NP*K)         proposal_ious  (B, NP, K)
//   [+, P*N_POINTS)     proposals_pred (P, N_POINTS)

static constexpr int NUM_PROPOSAL = 256;

static constexpr int CHUNK = 131072;          // floats per render block (512 KB out)
static constexpr int BM_WORDS = CHUNK / 32;   // 4096 words = 16 KB smem
static constexpr int THREADS = 512;           // 16 warps
static constexpr int WARPS = THREADS / 32;
static constexpr int TILES = BM_WORDS / 32;   // 128 warp-tiles per block

// ---------------------------------------------------------------------------
// Single fused kernel.
// Block 0: zero head region, then per-proposal scatter (sigmoid, b_idx, slot,
//          feats/mask/ious).
// Blocks 1..P*chunks: render one CHUNK of one proposals_pred row via smem
//          bitmap + warp-tile-transposed expansion (fully coalesced STG.128).
// ---------------------------------------------------------------------------
__global__ void __launch_bounds__(THREADS)
refnet_fused_kernel(
    const float* __restrict__ scores,   // (P,1)
    const float* __restrict__ feats,    // (P,FEAT)
    const float* __restrict__ ious,     // (P,K)
    const int2*  __restrict__ pidx,     // (M) pairs (pid, ptid)
    const int*   __restrict__ poff,     // (P+1,)
    const int*   __restrict__ boff,     // (B+1,)
    float* __restrict__ out,
    int P, int FEAT, int K, int B,
    long long off_mask, long long off_scores, long long off_ious, long long off_pp,
    long long n_points, int chunks_per_row)
{
    __shared__ unsigned int bm[BM_WORDS];

    int tid = threadIdx.x;

    if (blockIdx.x == 0) {
        // ---------------- head block ----------------
        // 1) zero [0, off_pp)
        long long n4 = off_pp >> 2;                 // off_pp is a multiple of 4
        float4* hz = (float4*)out;
        const float4 z4 = make_float4(0.f, 0.f, 0.f, 0.f);
        for (long long i = tid; i < n4; i += THREADS) hz[i] = z4;
        __syncthreads();

        // 2) per-proposal scatter (reuse bm as the b_idx array)
        int* b_arr = (int*)bm;
        int p = tid;
        if (p < P) {
            float s = scores[p];
            out[off_scores + p] = 1.0f / (1.0f + expf(-s));

            int o = poff[p];
            int first_pt = pidx[o].y;
            int b = 0;
            for (int i = 1; i <= B; ++i)
                if (boff[i] <= first_pt) b = i;     // searchsorted(right) - 1
            b_arr[p] = b;
        }
        __syncthreads();
        if (p < P) {
            int b = b_arr[p];
            int slot = 0;
            for (int q = 0; q < p; ++q) slot += (b_arr[q] == b);

            long long base = (long long)b * NUM_PROPOSAL + slot;
            out[off_mask + base] = 1.0f;

            const float* fsrc = feats + (long long)p * FEAT;
            float* fdst = out + base * FEAT;
            for (int i = 0; i < FEAT; ++i) fdst[i] = fsrc[i];

            const float* isrc = ious + (long long)p * K;
            float* idst = out + off_ious + base * K;
            for (int i = 0; i < K; ++i) idst[i] = isrc[i];
        }
        return;
    }

    // ---------------- render blocks ----------------
    int idx   = blockIdx.x - 1;
    int row   = idx / chunks_per_row;
    int chunk = idx % chunks_per_row;
    long long c0 = (long long)chunk * CHUNK;

    int warp = tid >> 5;
    int lane = tid & 31;

    // zero bitmap
    for (int w = tid; w < BM_WORDS; w += THREADS) bm[w] = 0u;
    __syncthreads();

    // set bits for this row's points falling in [c0, c0+CHUNK)
    int beg = poff[row], end = poff[row + 1];
    for (int i = beg + tid; i < end; i += THREADS) {
        int2 v = pidx[i];
        unsigned int rel = (unsigned int)(v.y - (int)c0);
        if (rel < (unsigned int)CHUNK) {
            atomicOr(&bm[rel >> 5], 1u << (rel & 31u));
        }
    }
    __syncthreads();

    // Expand: warp owns 32-word tiles (1024 floats = 4 KB each).
    // Iter j: lane L writes float4 #(j*32+L) -> consecutive lanes write
    // consecutive 16 B => each STG.128 is 512B contiguous.
    float* rowbase = out + off_pp + (long long)row * n_points + c0;
    long long row_rem = n_points - c0;        // floats available in this row chunk
    for (int t = warp; t < TILES; t += WARPS) {
        int wb = t * 32;                      // word base of tile
        long long fbase = (long long)wb * 32; // float base of tile
        if (fbase >= row_rem) break;
        float4* dst = (float4*)(rowbase + fbase);
        #pragma unroll
        for (int j = 0; j < 8; ++j) {
            int f = j * 32 + lane;                   // float4 index within tile
            unsigned int word = bm[wb + (f >> 3)];   // 8-lane smem broadcast
            unsigned int nib = (word >> ((f & 7) * 4)) & 0xFu;
            float4 o;
            o.x = (nib & 1u) ? 1.0f : 0.0f;
            o.y = (nib & 2u) ? 1.0f : 0.0f;
            o.z = (nib & 4u) ? 1.0f : 0.0f;
            o.w = (nib & 8u) ? 1.0f : 0.0f;
            __stcs(&dst[f], o);                      // streaming: evict-first
        }
    }
}

extern "C" void kernel_launch(void* const* d_in, const int* in_sizes, int n_in,
                              void* d_out, int out_size) {
    const float* scores = (const float*)d_in[0];
    const float* feats  = (const float*)d_in[1];
    const float* ious   = (const float*)d_in[2];
    const int*   pidx   = (const int*)d_in[3];
    const int*   poff   = (const int*)d_in[4];
    const int*   boff   = (const int*)d_in[5];

    int P    = in_sizes[0];               // 256
    int FEAT = in_sizes[1] / P;           // 16
    int K    = in_sizes[2] / P;           // 32
    int B    = in_sizes[5] - 1;           // 4

    long long off_mask   = (long long)B * NUM_PROPOSAL * FEAT;
    long long off_scores = off_mask  + (long long)B * NUM_PROPOSAL;
    long long off_ious   = off_scores + P;
    long long off_pp     = off_ious  + (long long)B * NUM_PROPOSAL * K;
    long long n_points   = ((long long)out_size - off_pp) / P;

    float* out = (float*)d_out;

    int chunks_per_row = (int)((n_points + CHUNK - 1) / CHUNK);
    int blocks = P * chunks_per_row + 1;   // +1 head block

    refnet_fused_kernel<<<blocks, THREADS>>>(
        scores, feats, ious, (const int2*)pidx, poff, boff, out,
        P, FEAT, K, B,
        off_mask, off_scores, off_ious, off_pp,
        n_points, chunks_per_row);
}